// round 10
// baseline (speedup 1.0000x reference)
#include <cuda_runtime.h>
#include <cuda_fp16.h>
#include <mma.h>

using namespace nvcuda;

#define D       128
#define D4      32
#define CAP     128         // bucket capacity; Poisson(32) => P(deg>128) ~ 1e-40
#define N_MAX   100000
#define E_MAX   3200000
#define EPSV    1e-5f

#define SAPAD   136         // half stride for smem tiles (272B: conflict-free ldmatrix)
#define SHPAD   132         // float stride for fp32 result tile

// ---------------- scratch (static device globals) --------------------------
__device__ int    g_cnt[N_MAX];
__device__ int    g_slot[(size_t)N_MAX * CAP];
__device__ __half g_featH[(size_t)N_MAX * D];
__device__ __half g_meanH[(size_t)N_MAX * D];
__device__ __half g_WH[D * D];
__device__ __half g_hH[(size_t)N_MAX * D];
__device__ float  g_colsum[D];
__device__ float  g_colsum2[D];

// ---------------- 1. zero accumulators -------------------------------------
__global__ void zero_kernel(int n) {
    int i = blockIdx.x * blockDim.x + threadIdx.x;
    if (i < n) g_cnt[i] = 0;
    if (i < D) { g_colsum[i] = 0.f; g_colsum2[i] = 0.f; }
}

// ---------------- 2. fused build: bucket scatter + feat->fp16 + W->fp16 ----
// scatter segment: 8 edges per thread for atomic MLP
__global__ void build_kernel(const int* __restrict__ src,
                             const int* __restrict__ dst, int e,
                             const float4* __restrict__ feat, int tot8,
                             const float4* __restrict__ W,
                             int scatB, int halfB) {
    int b = blockIdx.x, tid = threadIdx.x;
    if (b < scatB) {
        int base = (b * 256 + tid) * 8;
        if (base + 7 < e) {
            int4 d0 = *(const int4*)(dst + base);
            int4 d1 = *(const int4*)(dst + base + 4);
            int4 s0 = *(const int4*)(src + base);
            int4 s1 = *(const int4*)(src + base + 4);
            int p;
            p = atomicAdd(&g_cnt[d0.x], 1); if (p < CAP) g_slot[(size_t)d0.x * CAP + p] = s0.x;
            p = atomicAdd(&g_cnt[d0.y], 1); if (p < CAP) g_slot[(size_t)d0.y * CAP + p] = s0.y;
            p = atomicAdd(&g_cnt[d0.z], 1); if (p < CAP) g_slot[(size_t)d0.z * CAP + p] = s0.z;
            p = atomicAdd(&g_cnt[d0.w], 1); if (p < CAP) g_slot[(size_t)d0.w * CAP + p] = s0.w;
            p = atomicAdd(&g_cnt[d1.x], 1); if (p < CAP) g_slot[(size_t)d1.x * CAP + p] = s1.x;
            p = atomicAdd(&g_cnt[d1.y], 1); if (p < CAP) g_slot[(size_t)d1.y * CAP + p] = s1.y;
            p = atomicAdd(&g_cnt[d1.z], 1); if (p < CAP) g_slot[(size_t)d1.z * CAP + p] = s1.z;
            p = atomicAdd(&g_cnt[d1.w], 1); if (p < CAP) g_slot[(size_t)d1.w * CAP + p] = s1.w;
        } else {
            for (int j = base; j < e; j++) {
                int dd = dst[j];
                int p = atomicAdd(&g_cnt[dd], 1);
                if (p < CAP) g_slot[(size_t)dd * CAP + p] = src[j];
            }
        }
    } else if (b < scatB + halfB) {
        int i = (b - scatB) * 256 + tid;            // one per 8 floats
        if (i < tot8) {
            float4 a = feat[2 * i], c = feat[2 * i + 1];
            __half2 h0 = __floats2half2_rn(a.x, a.y);
            __half2 h1 = __floats2half2_rn(a.z, a.w);
            __half2 h2 = __floats2half2_rn(c.x, c.y);
            __half2 h3 = __floats2half2_rn(c.z, c.w);
            uint4 o;
            o.x = *(unsigned*)&h0; o.y = *(unsigned*)&h1;
            o.z = *(unsigned*)&h2; o.w = *(unsigned*)&h3;
            ((uint4*)g_featH)[i] = o;
        }
    } else {
        int i = (b - scatB - halfB) * 256 + tid;    // one per 8 W floats
        if (i < D * D / 8) {
            float4 a = W[2 * i], c = W[2 * i + 1];
            __half2 h0 = __floats2half2_rn(a.x, a.y);
            __half2 h1 = __floats2half2_rn(a.z, a.w);
            __half2 h2 = __floats2half2_rn(c.x, c.y);
            __half2 h3 = __floats2half2_rn(c.z, c.w);
            uint4 o;
            o.x = *(unsigned*)&h0; o.y = *(unsigned*)&h1;
            o.z = *(unsigned*)&h2; o.w = *(unsigned*)&h3;
            ((uint4*)g_WH)[i] = o;
        }
    }
}

// ---------------- 3. per-node mean aggregation (1 warp/node, 2x2 edges) -----
// 16 lanes cover one 256B row; halves take even/odd edges; each half runs two
// independent accumulator chains (stride 4) for 2x load MLP.
__global__ void gather_mean_kernel(int n) {
    int gw   = (blockIdx.x * blockDim.x + threadIdx.x) >> 5;
    int lane = threadIdx.x & 31;
    if (gw >= n) return;
    int deg = g_cnt[gw];
    if (deg > CAP) deg = CAP;
    size_t base = (size_t)gw * CAP;
    int half = lane >> 4;
    int sub  = lane & 15;
    const uint4* F = (const uint4*)g_featH;
    float a0=0.f,a1=0.f,a2=0.f,a3=0.f,a4=0.f,a5=0.f,a6=0.f,a7=0.f;
    float c0=0.f,c1=0.f,c2=0.f,c3=0.f,c4=0.f,c5=0.f,c6=0.f,c7=0.f;
    int i = half;
    for (; i + 2 < deg; i += 4) {
        int sr0 = g_slot[base + i];
        int sr1 = g_slot[base + i + 2];
        uint4 v0 = __ldg(&F[(size_t)sr0 * 16 + sub]);
        uint4 v1 = __ldg(&F[(size_t)sr1 * 16 + sub]);
        float2 f0 = __half22float2(*(__half2*)&v0.x);
        float2 f1 = __half22float2(*(__half2*)&v0.y);
        float2 f2 = __half22float2(*(__half2*)&v0.z);
        float2 f3 = __half22float2(*(__half2*)&v0.w);
        a0 += f0.x; a1 += f0.y; a2 += f1.x; a3 += f1.y;
        a4 += f2.x; a5 += f2.y; a6 += f3.x; a7 += f3.y;
        float2 g0 = __half22float2(*(__half2*)&v1.x);
        float2 g1 = __half22float2(*(__half2*)&v1.y);
        float2 g2 = __half22float2(*(__half2*)&v1.z);
        float2 g3 = __half22float2(*(__half2*)&v1.w);
        c0 += g0.x; c1 += g0.y; c2 += g1.x; c3 += g1.y;
        c4 += g2.x; c5 += g2.y; c6 += g3.x; c7 += g3.y;
    }
    for (; i < deg; i += 2) {
        int sr = g_slot[base + i];
        uint4 v = __ldg(&F[(size_t)sr * 16 + sub]);
        float2 f0 = __half22float2(*(__half2*)&v.x);
        float2 f1 = __half22float2(*(__half2*)&v.y);
        float2 f2 = __half22float2(*(__half2*)&v.z);
        float2 f3 = __half22float2(*(__half2*)&v.w);
        a0 += f0.x; a1 += f0.y; a2 += f1.x; a3 += f1.y;
        a4 += f2.x; a5 += f2.y; a6 += f3.x; a7 += f3.y;
    }
    a0 += c0; a1 += c1; a2 += c2; a3 += c3;
    a4 += c4; a5 += c5; a6 += c6; a7 += c7;
    a0 += __shfl_xor_sync(0xffffffffu, a0, 16);
    a1 += __shfl_xor_sync(0xffffffffu, a1, 16);
    a2 += __shfl_xor_sync(0xffffffffu, a2, 16);
    a3 += __shfl_xor_sync(0xffffffffu, a3, 16);
    a4 += __shfl_xor_sync(0xffffffffu, a4, 16);
    a5 += __shfl_xor_sync(0xffffffffu, a5, 16);
    a6 += __shfl_xor_sync(0xffffffffu, a6, 16);
    a7 += __shfl_xor_sync(0xffffffffu, a7, 16);
    if (half == 0) {
        float inv = 1.f / fmaxf((float)deg, 1.f);
        __half2 o0 = __floats2half2_rn(a0 * inv, a1 * inv);
        __half2 o1 = __floats2half2_rn(a2 * inv, a3 * inv);
        __half2 o2 = __floats2half2_rn(a4 * inv, a5 * inv);
        __half2 o3 = __floats2half2_rn(a6 * inv, a7 * inv);
        uint4 o;
        o.x = *(unsigned*)&o0; o.y = *(unsigned*)&o1;
        o.z = *(unsigned*)&o2; o.w = *(unsigned*)&o3;
        ((uint4*)g_meanH)[(size_t)gw * 16 + sub] = o;
    }
}

// ---------------- 4. persistent wmma GEMM: sW loaded once per block ---------
// grid = 2*SMs; block loops over 128-row tiles. sH (fp32, 64 rows) aliases sA
// only, so sW survives across tiles; epilogue runs in two 64-row passes.
__global__ void __launch_bounds__(256) gemm_kernel(const float* __restrict__ bias,
                                                   int n, int ntiles) {
    extern __shared__ char smem[];
    __half* sW = (__half*)smem;                           // 128 x SAPAD (34816 B)
    __half* sA = (__half*)(smem + 34816);                 // 128 x SAPAD (34816 B)
    float*  sH = (float*)(smem + 34816);                  // 64 x SHPAD fp32 (aliases sA)
    float*  s_sum  = (float*)(smem + 69632);
    float*  s_sum2 = (float*)(smem + 69632 + 512);

    int tid = threadIdx.x;
    int wid = tid >> 5;
    int wr = wid >> 1, wc = wid & 1;
    int cg = tid & 31, rg = tid >> 5;
    float4 bb = ((const float4*)bias)[cg];

    // load W once
    #pragma unroll
    for (int t = tid; t < 128 * 16; t += 256) {
        int r = t >> 4, c = t & 15;
        ((uint4*)(sW + r * SAPAD))[c] = ((const uint4*)g_WH)[r * 16 + c];
    }
    uint4 z4; z4.x = z4.y = z4.z = z4.w = 0u;

    for (int tile = blockIdx.x; tile < ntiles; tile += gridDim.x) {
        int row0 = tile * 128;
        __syncthreads();                                  // prev epilogue done; sW visible
        #pragma unroll
        for (int t = tid; t < 128 * 16; t += 256) {
            int r = t >> 4, c = t & 15;
            ((uint4*)(sA + r * SAPAD))[c] =
                (row0 + r < n) ? ((const uint4*)g_meanH)[(size_t)(row0 + r) * 16 + c] : z4;
        }
        if (tid < D) { s_sum[tid] = 0.f; s_sum2[tid] = 0.f; }
        __syncthreads();

        wmma::fragment<wmma::accumulator, 16, 16, 16, float> acc[2][4];
        #pragma unroll
        for (int i = 0; i < 2; i++)
            #pragma unroll
            for (int j = 0; j < 4; j++) wmma::fill_fragment(acc[i][j], 0.f);

        #pragma unroll
        for (int k = 0; k < D; k += 16) {
            wmma::fragment<wmma::matrix_a, 16, 16, 16, __half, wmma::row_major> fa[2];
            #pragma unroll
            for (int i = 0; i < 2; i++)
                wmma::load_matrix_sync(fa[i], sA + (wr * 32 + i * 16) * SAPAD + k, SAPAD);
            #pragma unroll
            for (int j = 0; j < 4; j++) {
                wmma::fragment<wmma::matrix_b, 16, 16, 16, __half, wmma::row_major> fb;
                wmma::load_matrix_sync(fb, sW + k * SAPAD + wc * 64 + j * 16, SAPAD);
                wmma::mma_sync(acc[0][j], fa[0], fb, acc[0][j]);
                wmma::mma_sync(acc[1][j], fa[1], fb, acc[1][j]);
            }
        }

        float ls0=0.f, ls1=0.f, ls2=0.f, ls3=0.f;
        float lq0=0.f, lq1=0.f, lq2=0.f, lq3=0.f;
        #pragma unroll
        for (int p = 0; p < 2; p++) {
            __syncthreads();                              // sA reads / pass-0 sH reads done
            if ((wr >> 1) == p) {
                int wr2 = wr & 1;                         // 0..1 within pass
                #pragma unroll
                for (int i = 0; i < 2; i++)
                    #pragma unroll
                    for (int j = 0; j < 4; j++)
                        wmma::store_matrix_sync(sH + (wr2 * 32 + i * 16) * SHPAD + wc * 64 + j * 16,
                                                acc[i][j], SHPAD, wmma::mem_row_major);
            }
            __syncthreads();
            #pragma unroll
            for (int i = 0; i < 8; i++) {
                int rl = rg * 8 + i;                      // 0..63
                int r = row0 + p * 64 + rl;
                if (r < n) {
                    float4 h = *(float4*)&sH[rl * SHPAD + cg * 4];
                    float x0 = h.x + bb.x, x1 = h.y + bb.y, x2 = h.z + bb.z, x3 = h.w + bb.w;
                    ls0 += x0; ls1 += x1; ls2 += x2; ls3 += x3;
                    lq0 += x0*x0; lq1 += x1*x1; lq2 += x2*x2; lq3 += x3*x3;
                    __half2 p0 = __floats2half2_rn(x0, x1);
                    __half2 p1 = __floats2half2_rn(x2, x3);
                    uint2 o; o.x = *(unsigned*)&p0; o.y = *(unsigned*)&p1;
                    ((uint2*)g_hH)[(size_t)r * 32 + cg] = o;
                }
            }
        }
        atomicAdd(&s_sum[4*cg+0], ls0);  atomicAdd(&s_sum[4*cg+1], ls1);
        atomicAdd(&s_sum[4*cg+2], ls2);  atomicAdd(&s_sum[4*cg+3], ls3);
        atomicAdd(&s_sum2[4*cg+0], lq0); atomicAdd(&s_sum2[4*cg+1], lq1);
        atomicAdd(&s_sum2[4*cg+2], lq2); atomicAdd(&s_sum2[4*cg+3], lq3);
        __syncthreads();
        if (tid < D) {
            atomicAdd(&g_colsum[tid],  s_sum[tid]);
            atomicAdd(&g_colsum2[tid], s_sum2[tid]);
        }
    }
}

// ---------------- 5. finalize (params folded in, fp16 h input) --------------
__global__ void finalize_kernel(const float4* __restrict__ feat,
                                float4* __restrict__ out,
                                const float* __restrict__ gamma,
                                const float* __restrict__ beta,
                                float inv_n, int n4) {
    __shared__ float ssc[D], ssh[D];
    if (threadIdx.x < D) {
        int j = threadIdx.x;
        float mu  = g_colsum[j]  * inv_n;
        float var = g_colsum2[j] * inv_n - mu * mu;
        float sc  = gamma[j] * rsqrtf(var + EPSV);
        ssc[j] = sc;
        ssh[j] = beta[j] - mu * sc;
    }
    __syncthreads();
    const uint2* H = (const uint2*)g_hH;
    for (int i = blockIdx.x * blockDim.x + threadIdx.x; i < n4;
         i += gridDim.x * blockDim.x) {
        int c = i & (D4 - 1);
        uint2 hv = H[i];
        float2 h0 = __half22float2(*(__half2*)&hv.x);
        float2 h1 = __half22float2(*(__half2*)&hv.y);
        float4 f = feat[i];
        float4 sc = *(float4*)&ssc[c * 4];
        float4 sh = *(float4*)&ssh[c * 4];
        float4 o;
        o.x = f.x + fmaxf(h0.x * sc.x + sh.x, 0.f);
        o.y = f.y + fmaxf(h0.y * sc.y + sh.y, 0.f);
        o.z = f.z + fmaxf(h1.x * sc.z + sh.z, 0.f);
        o.w = f.w + fmaxf(h1.y * sc.w + sh.w, 0.f);
        out[i] = o;
    }
}

// ---------------- launch -----------------------------------------------------
extern "C" void kernel_launch(void* const* d_in, const int* in_sizes, int n_in,
                              void* d_out, int out_size) {
    const float* feature = (const float*)d_in[0];
    const int*   src     = (const int*)d_in[1];
    const int*   dst     = (const int*)d_in[2];
    const float* W       = (const float*)d_in[3];
    const float* b       = (const float*)d_in[4];
    const float* gamma   = (const float*)d_in[5];
    const float* beta    = (const float*)d_in[6];
    float*       out     = (float*)d_out;

    int n  = in_sizes[0] / D;
    int e  = in_sizes[1];
    int n4 = n * D4;

    int tot8  = n * D / 8;
    int scatB = ((e + 7) / 8 + 255) / 256;
    int halfB = (tot8 + 255) / 256;
    int wB    = (D * D / 8 + 255) / 256;

    zero_kernel<<<(n + 255) / 256, 256>>>(n);
    build_kernel<<<scatB + halfB + wB, 256>>>(src, dst, e, (const float4*)feature,
                                              tot8, (const float4*)W, scatB, halfB);

    gather_mean_kernel<<<(n * 32 + 255) / 256, 256>>>(n);

    int ntiles = (n + 127) / 128;
    int grid = 296;                                      // 2 per SM (148 SMs)
    if (grid > ntiles) grid = ntiles;
    static const int GEMM_SMEM = 69632 + 1024;           // 70656
    cudaFuncSetAttribute(gemm_kernel, cudaFuncAttributeMaxDynamicSharedMemorySize, GEMM_SMEM);
    gemm_kernel<<<grid, 256, GEMM_SMEM>>>(b, n, ntiles);

    finalize_kernel<<<(n4 + 255) / 256, 256>>>((const float4*)feature, (float4*)out,
                                               gamma, beta, 1.f / (float)n, n4);
}